// round 16
// baseline (speedup 1.0000x reference)
#include <cuda_runtime.h>
#include <cuda_fp16.h>
#include <math.h>

#define NVOX 884736   // 96^3
#define NJ   866400   // 96*95*95
#define NDIV 857375   // 95^3

#define QSTRIDE 100   // half2 entries per padded row (>= W+4 for W<=96)
#define QROWS   9216  // max D*H rows (96*96)

// fused prep kernel block ranges (128 threads/block); div FIRST (longest latency)
#define NBD 6699      // ceil(NDIV/128)
#define NBM 6912      // NVOX/128  (mask + Q3..6 emit)
#define NBJ 6912      // NVOX/128  (curl + Q0..2 emit)

// pair-block counts for median kernel (128 threads/block, 2 voxels/thread)
#define PB0 3420      // ceil(96*95*48/128)
#define PB1 3420      // 95*96*48
#define PB2 3385      // ceil(95*95*48/128)
#define PBB 3456      // 96*96*48/128

// ---------------- scratch ----------------
__device__ float g_jx[NJ];
__device__ float g_jy[NJ];
__device__ float g_jz[NJ];
__device__ float g_bxm[NVOX];
__device__ float g_bym[NVOX];
__device__ __half2 g_q[7][QROWS * QSTRIDE];   // pre-paired fp16 rows, w-reflected halo
__device__ double g_acc[12];   // zero at load; finalize resets after reading
// 0..2: (med-j)^2 jx,jy,jz ; 3..6: bxm,bym,bxp,byp ; 7 S1p, 8 S2p, 9 S1t, 10 S2t

// ---------------- staggered-pair emit helpers ----------------
// Padded row semantics: xp[p] = x[reflect(p-2)], p = 0..W+3.
// Q[k] = (xp[k], xp[k+1]).  Median pair (w0,w0+1) reads Q[w0..w0+4].
__device__ __forceinline__ void store_q(__half* qh, int row2, int p, int pmax, __half val) {
    if (p <= pmax) qh[row2 + 2*p] = val;                        // lo of Q[p]
    int pm1 = p - 1;
    if (pm1 >= 0 && pm1 <= pmax) qh[row2 + 2*pm1 + 1] = val;    // hi of Q[p-1]
}

__device__ __forceinline__ void emit_q(int field, int row, int w, int W, float valf) {
    __half* qh = (__half*)g_q[field];
    int row2 = row * (2 * QSTRIDE);
    __half val = __float2half_rn(valf);
    int pmax = W + 3;
    store_q(qh, row2, w + 2, pmax, val);
    if (w == 1)     store_q(qh, row2, 1,     pmax, val);   // xp[1]   = x[1]
    if (w == 2)     store_q(qh, row2, 0,     pmax, val);   // xp[0]   = x[2]
    if (w == W - 2) store_q(qh, row2, W + 2, pmax, val);   // xp[W+2] = x[W-2]
    if (w == W - 3) store_q(qh, row2, W + 3, pmax, val);   // xp[W+3] = x[W-3]
}

__device__ __forceinline__ void masked_b(const float* __restrict__ pb,
                                         const float* __restrict__ tg,
                                         int off, float& bx, float& by) {
    float xp = pb[off], yp = pb[off + NVOX];
    float xt = tg[off], yt = tg[off + NVOX];
    float m = (xp * xt + yp * yt > 0.0f) ? 1.0f : -1.0f;
    bx = xt * m;
    by = yt * m;
}

// ---------------- flux ----------------
__device__ __forceinline__ float flux_fn(const float* bx, const float* by,
                                         const float* bz, const float* z) {
    const float C3 = 1.0f / 3.0f;
    const float C6 = 1.0f / 6.0f;
    float f =
      0.25f*(bx[4]+bx[6]+bx[5]+bx[7]) * 0.5f*(fabsf(z[5]-z[4]) + fabsf(z[7]-z[6]))
    - 0.25f*(bx[0]+bx[2]+bx[1]+bx[3]) * 0.5f*(fabsf(z[1]-z[0]) + fabsf(z[3]-z[2]))
    + 0.25f*(by[2]+by[6]+by[3]+by[7]) * 0.5f*(fabsf(z[3]-z[2]) + fabsf(z[7]-z[6]))
    - 0.25f*(by[0]+by[4]+by[1]+by[5]) * 0.5f*(fabsf(z[1]-z[0]) + fabsf(z[5]-z[4]))
    + 0.5f*((bz[1]+bz[5]+bz[7])*C3 + (bz[1]+bz[7]+bz[3])*C3)
    - 0.5f*((bz[0]+bz[4]+bz[6])*C3 + (bz[0]+bz[6]+bz[2])*C3)
    + (bx[1]+bx[5]+bx[7])*(z[1]-z[5])*C6
    + (bx[1]+bx[3]+bx[7])*(z[3]-z[7])*C6
    + (by[1]+by[5]+by[7])*(z[5]-z[7])*C6
    + (by[1]+by[3]+by[7])*(z[1]-z[3])*C6
    - ( (bx[0]+bx[4]+bx[6])*(z[0]-z[4])*C6
      + (bx[0]+bx[2]+bx[6])*(z[2]-z[6])*C6
      + (by[0]+by[4]+by[6])*(z[4]-z[6])*C6
      + (by[0]+by[2]+by[6])*(z[0]-z[2])*C6 );
    return f;
}

__device__ __forceinline__ float aveb_fn(const float* bx, const float* by, const float* bz) {
    float sx = bx[0]+bx[1]+bx[2]+bx[3]+bx[4]+bx[5]+bx[6]+bx[7];
    float sy = by[0]+by[1]+by[2]+by[3]+by[4]+by[5]+by[6]+by[7];
    float sz = bz[0]+bz[1]+bz[2]+bz[3]+bz[4]+bz[5]+bz[6]+bz[7];
    sx *= 0.125f; sy *= 0.125f; sz *= 0.125f;
    return sx*sx + sy*sy + sz*sz + 1e-08f;
}

__device__ __forceinline__ double warp_red(double v) {
    #pragma unroll
    for (int o = 16; o > 0; o >>= 1)
        v += __shfl_down_sync(0xFFFFFFFFu, v, o);
    return v;
}

__device__ __forceinline__ float warp_redf(float v) {
    #pragma unroll
    for (int o = 16; o > 0; o >>= 1)
        v += __shfl_down_sync(0xFFFFFFFFu, v, o);
    return v;
}

// ---------------- FUSED prep kernel: divergence | mask | curl ----------------
#define IDX96(d,h,w) ((d)*9216 + (h)*96 + (w))

__global__ __launch_bounds__(128)
void prep_all_kernel(const float* __restrict__ pb,
                     const float* __restrict__ pz,
                     const float* __restrict__ tg) {
    __shared__ float sm[4][4];
    int b = blockIdx.x;

    if (b < NBD) {
        // ---- divergence branch (scheduled FIRST: longest-latency blocks) ----
        int i = b * 128 + threadIdx.x;
        float s1p = 0.0f, s2p = 0.0f, s1t = 0.0f, s2t = 0.0f;
        if (i < NDIV) {
            int d = i / 9025;
            int r = i - d * 9025;
            int h = r / 95;
            int w = r - h * 95;
            float bxp[8], byp[8], bzt[8], zz[8], bxm[8], bym[8];
            int c = 0;
            #pragma unroll
            for (int ii = 0; ii < 2; ii++)
            #pragma unroll
            for (int jj = 0; jj < 2; jj++)
            #pragma unroll
            for (int ll = 0; ll < 2; ll++) {
                int off = (d+ii)*9216 + (h+jj)*96 + (w+ll);
                float xp = pb[off], yp = pb[off + NVOX];
                float xt = tg[off], yt = tg[off + NVOX];
                bzt[c] = tg[off + 2*NVOX];
                zz[c]  = pz[off];
                float m = (xp*xt + yp*yt > 0.0f) ? 1.0f : -1.0f;
                bxp[c] = xp; byp[c] = yp;
                bxm[c] = xt * m; bym[c] = yt * m;
                c++;
            }
            {
                float f  = flux_fn(bxp, byp, bzt, zz);
                float ab = aveb_fn(bxp, byp, bzt);
                float r2 = f * f;
                float fl = __fdividef(r2 * r2, ab);
                s1p = fl;
                s2p = fl * fl;
            }
            {
                float f  = flux_fn(bxm, bym, bzt, zz);
                float ab = aveb_fn(bxm, bym, bzt);
                float r2 = f * f;
                float fl = __fdividef(r2 * r2, ab);
                s1t = fl;
                s2t = fl * fl;
            }
        }
        s1p = warp_redf(s1p); s2p = warp_redf(s2p);
        s1t = warp_redf(s1t); s2t = warp_redf(s2t);
        int wid = threadIdx.x >> 5;
        if ((threadIdx.x & 31) == 0) {
            sm[wid][0] = s1p; sm[wid][1] = s2p; sm[wid][2] = s1t; sm[wid][3] = s2t;
        }
        __syncthreads();
        if (threadIdx.x == 0) {
            double a0 = (double)sm[0][0] + sm[1][0] + sm[2][0] + sm[3][0];
            double a1 = (double)sm[0][1] + sm[1][1] + sm[2][1] + sm[3][1];
            double a2 = (double)sm[0][2] + sm[1][2] + sm[2][2] + sm[3][2];
            double a3 = (double)sm[0][3] + sm[1][3] + sm[2][3] + sm[3][3];
            atomicAdd(&g_acc[7],  a0);
            atomicAdd(&g_acc[8],  a1);
            atomicAdd(&g_acc[9],  a2);
            atomicAdd(&g_acc[10], a3);
        }
        return;
    }

    if (b < NBD + NBM) {
        // ---- mask branch: bxm/bym arrays + Q3..Q6 emits ----
        int i = (b - NBD) * 128 + threadIdx.x;
        float bxp = pb[i],        byp = pb[i + NVOX];
        float bxt = tg[i],        byt = tg[i + NVOX];
        float m = (bxp * bxt + byp * byt > 0.0f) ? 1.0f : -1.0f;
        float vx = bxt * m, vy = byt * m;
        g_bxm[i] = vx;
        g_bym[i] = vy;
        int row = i / 96;          // (d*96 + h), W = 96
        int w   = i - row * 96;
        emit_q(3, row, w, 96, vx);
        emit_q(4, row, w, 96, vy);
        emit_q(5, row, w, 96, bxp);
        emit_q(6, row, w, 96, byp);
        return;
    }

    // ---- curl branch: jx/jy/jz arrays + Q0..Q2 emits (mask recomputed inline) ----
    {
        int i = (b - NBD - NBM) * 128 + threadIdx.x;
        const float* bzp = pb + 2 * NVOX;
        int d = i / 9216;
        int r = i - d * 9216;
        int h = r / 96;
        int w = r - h * 96;

        if (h < 95 && w < 95) {    // jx: (96,95,95)
            float bz00 = bzp[IDX96(d,h,w)],   bz01 = bzp[IDX96(d,h,w+1)];
            float bz10 = bzp[IDX96(d,h+1,w)], bz11 = bzp[IDX96(d,h+1,w+1)];
            float t0, by00, t1, by01, t2, by10, t3, by11;
            masked_b(pb, tg, IDX96(d,h,w),     t0, by00);
            masked_b(pb, tg, IDX96(d,h,w+1),   t1, by01);
            masked_b(pb, tg, IDX96(d,h+1,w),   t2, by10);
            masked_b(pb, tg, IDX96(d,h+1,w+1), t3, by11);
            float jx = 0.5f*((bz00 - bz10) + (bz01 - bz11))
                     - 0.5f*((by00 - by01) + (by10 - by11));
            g_jx[(d*95 + h)*95 + w] = jx;
            emit_q(0, d*95 + h, w, 95, jx);
        }
        if (d < 95 && w < 95) {    // jy: (95,96,95)
            float bx00, u0, bx01, u1, bx10, u2, bx11, u3;
            masked_b(pb, tg, IDX96(d,h,w),     bx00, u0);
            masked_b(pb, tg, IDX96(d,h,w+1),   bx01, u1);
            masked_b(pb, tg, IDX96(d+1,h,w),   bx10, u2);
            masked_b(pb, tg, IDX96(d+1,h,w+1), bx11, u3);
            float bz00 = bzp[IDX96(d,h,w)],   bz01 = bzp[IDX96(d,h,w+1)];
            float bz10 = bzp[IDX96(d+1,h,w)], bz11 = bzp[IDX96(d+1,h,w+1)];
            float jy = 0.5f*((bx00 - bx01) + (bx10 - bx11))
                     - 0.5f*((bz00 - bz10) + (bz01 - bz11));
            g_jy[(d*96 + h)*95 + w] = jy;
            emit_q(1, d*96 + h, w, 95, jy);
        }
        if (d < 95 && h < 95) {    // jz: (95,95,96)
            float bx00, by00, bx01, by01, bx10, by10, bx11, by11;
            masked_b(pb, tg, IDX96(d,h,w),     bx00, by00);
            masked_b(pb, tg, IDX96(d,h+1,w),   bx01, by01);
            masked_b(pb, tg, IDX96(d+1,h,w),   bx10, by10);
            masked_b(pb, tg, IDX96(d+1,h+1,w), bx11, by11);
            float jz = 0.5f*((by00 - by10) + (by01 - by11))
                     - 0.5f*((bx00 - bx01) + (bx10 - bx11));
            g_jz[(d*95 + h)*96 + w] = jz;
            emit_q(2, d*95 + h, w, 96, jz);
        }
    }
}

// ---------------- packed compare-exchange: alu (HMNMX2) and fma-pipe emu ----------------
template<bool ASC>
__device__ __forceinline__ void ce2s(__half2& a, __half2& b) {
    __half2 mn = __hmin2(a, b);
    __half2 mx = __hmax2(a, b);
    if (ASC) { a = mn; b = mx; } else { a = mx; b = mn; }
}

// fma-pipe comparator: mn = (a+b)/2 - |a-b|/2, mx = (a+b)/2 + |a-b|/2.
// <=1.5 fp16 ulp; NEVER sees +inf (pads excluded by the prune invariant).
template<bool ASC>
__device__ __forceinline__ void ce2e(__half2& a, __half2& b) {
    const __half2 H05 = __floats2half2_rn(0.5f, 0.5f);
    const __half2 M05 = __floats2half2_rn(-0.5f, -0.5f);
    __half2 s2 = __hmul2(__hadd2(a, b), H05);
    __half2 ad = __habs2(__hsub2(a, b));
    __half2 mn = __hfma2(ad, M05, s2);
    __half2 mx = __hfma2(ad, H05, s2);
    if (ASC) { a = mn; b = mx; } else { a = mx; b = mn; }
}

// 37.5% of comparators ((lo&7)<3: same &-mask family as the r10-proven 25%
// pattern, fraction moved toward the measured pipe-balance point f* ~ 0.39)
// go to the fma pipe.
template<bool ASC>
__device__ __forceinline__ void ce2sel(__half2& a, __half2& b, int lowire) {
    if ((lowire & 7) < 3) ce2e<ASC>(a, b);
    else                  ce2s<ASC>(a, b);
}

// Batcher OEM, template-constant indices only (register-resident).
// Pad prune: wires >= 125 hold +inf pads that never move under ascending
// comparators; any comparator whose HIGH wire is >= 125 is an exact no-op.
template<int LO, int N, int R, bool ASC>
__device__ __forceinline__ void oem_merge(__half2* v) {
    constexpr int M = 2 * R;
    if constexpr (M < N) {
        oem_merge<LO,     N, M, ASC>(v);
        oem_merge<LO + R, N, M, ASC>(v);
        #pragma unroll
        for (int i = LO + R; i + R < LO + N; i += M)
            if (i + R < 125) ce2sel<ASC>(v[i], v[i + R], i);
    } else {
        if constexpr (LO + R < 125) ce2sel<ASC>(v[LO], v[LO + R], LO);
    }
}

template<int LO, int N, bool ASC>
__device__ __forceinline__ void oem_sort(__half2* v) {
    if constexpr (N > 1) {
        oem_sort<LO,       N/2, ASC>(v);
        oem_sort<LO + N/2, N/2, ASC>(v);
        oem_merge<LO, N, 1, ASC>(v);
    }
}

// ---------------- fused median kernel ----------------
__device__ __forceinline__ const float* med_src(const float* pb, int sel) {
    switch (sel) {
        case 0: return g_jx;
        case 1: return g_jy;
        case 2: return g_jz;
        case 3: return g_bxm;
        case 4: return g_bym;
        case 5: return pb;            // bx_p
        default: return pb + NVOX;    // by_p
    }
}

__global__ __launch_bounds__(128)
void median_all_kernel(const float* __restrict__ pb) {
    int b = blockIdx.x;
    int sel, base;
    if      (b < PB0)                       { sel = 0; base = b; }
    else if (b < PB0+PB1)                   { sel = 1; base = b - PB0; }
    else if (b < PB0+PB1+PB2)               { sel = 2; base = b - (PB0+PB1); }
    else if (b < PB0+PB1+PB2+1*PBB)         { sel = 3; base = b - (PB0+PB1+PB2); }
    else if (b < PB0+PB1+PB2+2*PBB)         { sel = 4; base = b - (PB0+PB1+PB2+1*PBB); }
    else if (b < PB0+PB1+PB2+3*PBB)         { sel = 5; base = b - (PB0+PB1+PB2+2*PBB); }
    else                                    { sel = 6; base = b - (PB0+PB1+PB2+3*PBB); }

    int D, H, W;
    if      (sel == 0) { D = 96; H = 95; W = 95; }
    else if (sel == 1) { D = 95; H = 96; W = 95; }
    else if (sel == 2) { D = 95; H = 95; W = 96; }
    else               { D = 96; H = 96; W = 96; }

    const int PW = 48;
    int npairs = D * H * PW;

    int i = base * 128 + threadIdx.x;
    double local = 0.0;
    if (i < npairs) {
        int hp = H * PW;
        int d = i / hp;
        int r = i - d * hp;
        int h = r / PW;
        int t = r - h * PW;
        int w0 = 2 * t;
        bool have1 = (w0 + 1 < W);

        int rd[5], rh[5];
        #pragma unroll
        for (int o = 0; o < 5; o++) {
            int c;
            c = d + o - 2; rd[o] = (c < 0) ? -c : ((c >= D) ? 2*D - 2 - c : c);
            c = h + o - 2; rh[o] = (c < 0) ? -c : ((c >= H) ? 2*H - 2 - c : c);
        }

        // exact fp32 centers
        const float* __restrict__ src = med_src(pb, sel);
        const float* crow = src + (d*H + h) * W + w0;
        float c0f = __ldg(crow);
        float c1f = have1 ? __ldg(crow + 1) : 0.0f;

        // pre-paired fp16 window loads: Q[w0 + o], o = 0..4 per row
        const __half2* __restrict__ q = g_q[sel];
        __half2 v[128];
        int idx = 0;
        #pragma unroll
        for (int dd = 0; dd < 5; dd++) {
            #pragma unroll
            for (int hh = 0; hh < 5; hh++) {
                const __half2* qrow = q + (rd[dd]*H + rh[hh]) * QSTRIDE + w0;
                v[idx++] = qrow[0];
                v[idx++] = qrow[1];
                v[idx++] = qrow[2];
                v[idx++] = qrow[3];
                v[idx++] = qrow[4];
            }
        }
        const float FINF = __int_as_float(0x7f800000);
        __half2 INF2 = __floats2half2_rn(FINF, FINF);
        v[125] = INF2; v[126] = INF2; v[127] = INF2;

        // Batcher OEM, both ascending; pads pinned at v[125..127] (pruned).
        oem_sort<0,  64, true>(v);
        oem_sort<64, 64, true>(v);

        // rank-63 (1-based) of A = v[0..62] U B = v[64..124]:
        //   med = min( v[62], min over i=2..62 of max(v[i-1], v[126-i]) )
        __half2 m0 = __hmax2(v[1], v[124]);
        __half2 m1 = __hmax2(v[2], v[123]);
        __half2 m2 = __hmax2(v[3], v[122]);
        __half2 m3 = __hmax2(v[4], v[121]);
        #pragma unroll
        for (int t2 = 6; t2 <= 62; t2 += 4) {
            m0 = __hmin2(m0, __hmax2(v[t2-1], v[126-t2]));
            if (t2+1 <= 62) m1 = __hmin2(m1, __hmax2(v[t2],   v[125-t2]));
            if (t2+2 <= 62) m2 = __hmin2(m2, __hmax2(v[t2+1], v[124-t2]));
            if (t2+3 <= 62) m3 = __hmin2(m3, __hmax2(v[t2+2], v[123-t2]));
        }
        __half2 med2 = __hmin2(__hmin2(m0, m1),
                               __hmin2(m2, __hmin2(m3, v[62])));

        float med0 = __low2float(med2);
        float med1 = __high2float(med2);
        float d0 = med0 - c0f;
        local = (double)(d0 * d0);
        if (have1) {
            float d1 = med1 - c1f;
            local += (double)(d1 * d1);
        }
    }
    local = warp_red(local);
    if ((threadIdx.x & 31) == 0) atomicAdd(&g_acc[sel], local);
}

// ---------------- finalize (reads accumulators, then resets them; static
// zero-init makes the very first call correct) ----------------
__global__ void finalize_kernel(float* __restrict__ out, int out_size) {
    if (blockIdx.x != 0 || threadIdx.x != 0) return;
    double n95 = (double)NDIV;
    double mp = g_acc[7] / n95;
    double mt = g_acc[9] / n95;
    double o[6];
    o[0] = mp;
    o[1] = g_acc[8] / n95 - mp * mp;
    o[2] = mt;
    o[3] = g_acc[10] / n95 - mt * mt;
    o[4] = (g_acc[0] + g_acc[1] + g_acc[2]) / (double)NJ;
    o[5] = (g_acc[3] + g_acc[4] + g_acc[5] + g_acc[6]) / (double)NVOX;
    for (int k = 0; k < 6 && k < out_size; k++) out[k] = (float)o[k];
    #pragma unroll
    for (int k = 0; k < 12; k++) g_acc[k] = 0.0;
}

// ---------------- launch ----------------
extern "C" void kernel_launch(void* const* d_in, const int* in_sizes, int n_in,
                              void* d_out, int out_size) {
    const float* pb = (const float*)d_in[0];   // pred_b  (3,96^3)
    const float* pz = (const float*)d_in[1];   // pred_z  (96^3)
    const float* tg = (const float*)d_in[2];   // targets (3,96^3)
    float* out = (float*)d_out;

    prep_all_kernel<<<NBD + NBM + NBJ, 128>>>(pb, pz, tg);
    median_all_kernel<<<PB0 + PB1 + PB2 + 4*PBB, 128>>>(pb);
    finalize_kernel<<<1, 32>>>(out, out_size);
}

// round 17
// speedup vs baseline: 1.1533x; 1.1533x over previous
#include <cuda_runtime.h>
#include <cuda_fp16.h>
#include <math.h>

#define NVOX 884736   // 96^3
#define NJ   866400   // 96*95*95
#define NDIV 857375   // 95^3

#define QSTRIDE 100   // half2 entries per padded row (>= W+4 for W<=96)
#define QROWS   9216  // max D*H rows (96*96)

// fused prep kernel block ranges (128 threads/block); div FIRST (longest latency)
#define NBD 6699      // ceil(NDIV/128)
#define NBM 6912      // NVOX/128  (mask + Q3..6 emit)
#define NBJ 6912      // NVOX/128  (curl + Q0..2 emit)

// pair-block counts for median kernel (128 threads/block, 2 voxels/thread)
#define PB0 3420      // ceil(96*95*48/128)
#define PB1 3420      // 95*96*48
#define PB2 3385      // ceil(95*95*48/128)
#define PBB 3456      // 96*96*48/128

// ---------------- scratch ----------------
__device__ float g_jx[NJ];
__device__ float g_jy[NJ];
__device__ float g_jz[NJ];
__device__ float g_bxm[NVOX];
__device__ float g_bym[NVOX];
__device__ __half2 g_q[7][QROWS * QSTRIDE];   // pre-paired fp16 rows, w-reflected halo
__device__ double g_acc[12];   // zero at load; finalize resets after reading
// 0..2: (med-j)^2 jx,jy,jz ; 3..6: bxm,bym,bxp,byp ; 7 S1p, 8 S2p, 9 S1t, 10 S2t

// ---------------- staggered-pair emit helpers ----------------
// Padded row semantics: xp[p] = x[reflect(p-2)], p = 0..W+3.
// Q[k] = (xp[k], xp[k+1]).  Median pair (w0,w0+1) reads Q[w0..w0+4].
__device__ __forceinline__ void store_q(__half* qh, int row2, int p, int pmax, __half val) {
    if (p <= pmax) qh[row2 + 2*p] = val;                        // lo of Q[p]
    int pm1 = p - 1;
    if (pm1 >= 0 && pm1 <= pmax) qh[row2 + 2*pm1 + 1] = val;    // hi of Q[p-1]
}

__device__ __forceinline__ void emit_q(int field, int row, int w, int W, float valf) {
    __half* qh = (__half*)g_q[field];
    int row2 = row * (2 * QSTRIDE);
    __half val = __float2half_rn(valf);
    int pmax = W + 3;
    store_q(qh, row2, w + 2, pmax, val);
    if (w == 1)     store_q(qh, row2, 1,     pmax, val);   // xp[1]   = x[1]
    if (w == 2)     store_q(qh, row2, 0,     pmax, val);   // xp[0]   = x[2]
    if (w == W - 2) store_q(qh, row2, W + 2, pmax, val);   // xp[W+2] = x[W-2]
    if (w == W - 3) store_q(qh, row2, W + 3, pmax, val);   // xp[W+3] = x[W-3]
}

__device__ __forceinline__ void masked_b(const float* __restrict__ pb,
                                         const float* __restrict__ tg,
                                         int off, float& bx, float& by) {
    float xp = pb[off], yp = pb[off + NVOX];
    float xt = tg[off], yt = tg[off + NVOX];
    float m = (xp * xt + yp * yt > 0.0f) ? 1.0f : -1.0f;
    bx = xt * m;
    by = yt * m;
}

// ---------------- flux ----------------
__device__ __forceinline__ float flux_fn(const float* bx, const float* by,
                                         const float* bz, const float* z) {
    const float C3 = 1.0f / 3.0f;
    const float C6 = 1.0f / 6.0f;
    float f =
      0.25f*(bx[4]+bx[6]+bx[5]+bx[7]) * 0.5f*(fabsf(z[5]-z[4]) + fabsf(z[7]-z[6]))
    - 0.25f*(bx[0]+bx[2]+bx[1]+bx[3]) * 0.5f*(fabsf(z[1]-z[0]) + fabsf(z[3]-z[2]))
    + 0.25f*(by[2]+by[6]+by[3]+by[7]) * 0.5f*(fabsf(z[3]-z[2]) + fabsf(z[7]-z[6]))
    - 0.25f*(by[0]+by[4]+by[1]+by[5]) * 0.5f*(fabsf(z[1]-z[0]) + fabsf(z[5]-z[4]))
    + 0.5f*((bz[1]+bz[5]+bz[7])*C3 + (bz[1]+bz[7]+bz[3])*C3)
    - 0.5f*((bz[0]+bz[4]+bz[6])*C3 + (bz[0]+bz[6]+bz[2])*C3)
    + (bx[1]+bx[5]+bx[7])*(z[1]-z[5])*C6
    + (bx[1]+bx[3]+bx[7])*(z[3]-z[7])*C6
    + (by[1]+by[5]+by[7])*(z[5]-z[7])*C6
    + (by[1]+by[3]+by[7])*(z[1]-z[3])*C6
    - ( (bx[0]+bx[4]+bx[6])*(z[0]-z[4])*C6
      + (bx[0]+bx[2]+bx[6])*(z[2]-z[6])*C6
      + (by[0]+by[4]+by[6])*(z[4]-z[6])*C6
      + (by[0]+by[2]+by[6])*(z[0]-z[2])*C6 );
    return f;
}

__device__ __forceinline__ float aveb_fn(const float* bx, const float* by, const float* bz) {
    float sx = bx[0]+bx[1]+bx[2]+bx[3]+bx[4]+bx[5]+bx[6]+bx[7];
    float sy = by[0]+by[1]+by[2]+by[3]+by[4]+by[5]+by[6]+by[7];
    float sz = bz[0]+bz[1]+bz[2]+bz[3]+bz[4]+bz[5]+bz[6]+bz[7];
    sx *= 0.125f; sy *= 0.125f; sz *= 0.125f;
    return sx*sx + sy*sy + sz*sz + 1e-08f;
}

__device__ __forceinline__ double warp_red(double v) {
    #pragma unroll
    for (int o = 16; o > 0; o >>= 1)
        v += __shfl_down_sync(0xFFFFFFFFu, v, o);
    return v;
}

__device__ __forceinline__ float warp_redf(float v) {
    #pragma unroll
    for (int o = 16; o > 0; o >>= 1)
        v += __shfl_down_sync(0xFFFFFFFFu, v, o);
    return v;
}

// ---------------- FUSED prep kernel: divergence | mask | curl ----------------
#define IDX96(d,h,w) ((d)*9216 + (h)*96 + (w))

__global__ __launch_bounds__(128)
void prep_all_kernel(const float* __restrict__ pb,
                     const float* __restrict__ pz,
                     const float* __restrict__ tg) {
    __shared__ float sm[4][4];
    int b = blockIdx.x;

    if (b < NBD) {
        // ---- divergence branch (scheduled FIRST: longest-latency blocks) ----
        int i = b * 128 + threadIdx.x;
        float s1p = 0.0f, s2p = 0.0f, s1t = 0.0f, s2t = 0.0f;
        if (i < NDIV) {
            int d = i / 9025;
            int r = i - d * 9025;
            int h = r / 95;
            int w = r - h * 95;
            float bxp[8], byp[8], bzt[8], zz[8], bxm[8], bym[8];
            int c = 0;
            #pragma unroll
            for (int ii = 0; ii < 2; ii++)
            #pragma unroll
            for (int jj = 0; jj < 2; jj++)
            #pragma unroll
            for (int ll = 0; ll < 2; ll++) {
                int off = (d+ii)*9216 + (h+jj)*96 + (w+ll);
                float xp = pb[off], yp = pb[off + NVOX];
                float xt = tg[off], yt = tg[off + NVOX];
                bzt[c] = tg[off + 2*NVOX];
                zz[c]  = pz[off];
                float m = (xp*xt + yp*yt > 0.0f) ? 1.0f : -1.0f;
                bxp[c] = xp; byp[c] = yp;
                bxm[c] = xt * m; bym[c] = yt * m;
                c++;
            }
            {
                float f  = flux_fn(bxp, byp, bzt, zz);
                float ab = aveb_fn(bxp, byp, bzt);
                float r2 = f * f;
                float fl = __fdividef(r2 * r2, ab);
                s1p = fl;
                s2p = fl * fl;
            }
            {
                float f  = flux_fn(bxm, bym, bzt, zz);
                float ab = aveb_fn(bxm, bym, bzt);
                float r2 = f * f;
                float fl = __fdividef(r2 * r2, ab);
                s1t = fl;
                s2t = fl * fl;
            }
        }
        s1p = warp_redf(s1p); s2p = warp_redf(s2p);
        s1t = warp_redf(s1t); s2t = warp_redf(s2t);
        int wid = threadIdx.x >> 5;
        if ((threadIdx.x & 31) == 0) {
            sm[wid][0] = s1p; sm[wid][1] = s2p; sm[wid][2] = s1t; sm[wid][3] = s2t;
        }
        __syncthreads();
        if (threadIdx.x == 0) {
            double a0 = (double)sm[0][0] + sm[1][0] + sm[2][0] + sm[3][0];
            double a1 = (double)sm[0][1] + sm[1][1] + sm[2][1] + sm[3][1];
            double a2 = (double)sm[0][2] + sm[1][2] + sm[2][2] + sm[3][2];
            double a3 = (double)sm[0][3] + sm[1][3] + sm[2][3] + sm[3][3];
            atomicAdd(&g_acc[7],  a0);
            atomicAdd(&g_acc[8],  a1);
            atomicAdd(&g_acc[9],  a2);
            atomicAdd(&g_acc[10], a3);
        }
        return;
    }

    if (b < NBD + NBM) {
        // ---- mask branch: bxm/bym arrays + Q3..Q6 emits ----
        int i = (b - NBD) * 128 + threadIdx.x;
        float bxp = pb[i],        byp = pb[i + NVOX];
        float bxt = tg[i],        byt = tg[i + NVOX];
        float m = (bxp * bxt + byp * byt > 0.0f) ? 1.0f : -1.0f;
        float vx = bxt * m, vy = byt * m;
        g_bxm[i] = vx;
        g_bym[i] = vy;
        int row = i / 96;          // (d*96 + h), W = 96
        int w   = i - row * 96;
        emit_q(3, row, w, 96, vx);
        emit_q(4, row, w, 96, vy);
        emit_q(5, row, w, 96, bxp);
        emit_q(6, row, w, 96, byp);
        return;
    }

    // ---- curl branch: jx/jy/jz arrays + Q0..Q2 emits (mask recomputed inline) ----
    {
        int i = (b - NBD - NBM) * 128 + threadIdx.x;
        const float* bzp = pb + 2 * NVOX;
        int d = i / 9216;
        int r = i - d * 9216;
        int h = r / 96;
        int w = r - h * 96;

        if (h < 95 && w < 95) {    // jx: (96,95,95)
            float bz00 = bzp[IDX96(d,h,w)],   bz01 = bzp[IDX96(d,h,w+1)];
            float bz10 = bzp[IDX96(d,h+1,w)], bz11 = bzp[IDX96(d,h+1,w+1)];
            float t0, by00, t1, by01, t2, by10, t3, by11;
            masked_b(pb, tg, IDX96(d,h,w),     t0, by00);
            masked_b(pb, tg, IDX96(d,h,w+1),   t1, by01);
            masked_b(pb, tg, IDX96(d,h+1,w),   t2, by10);
            masked_b(pb, tg, IDX96(d,h+1,w+1), t3, by11);
            float jx = 0.5f*((bz00 - bz10) + (bz01 - bz11))
                     - 0.5f*((by00 - by01) + (by10 - by11));
            g_jx[(d*95 + h)*95 + w] = jx;
            emit_q(0, d*95 + h, w, 95, jx);
        }
        if (d < 95 && w < 95) {    // jy: (95,96,95)
            float bx00, u0, bx01, u1, bx10, u2, bx11, u3;
            masked_b(pb, tg, IDX96(d,h,w),     bx00, u0);
            masked_b(pb, tg, IDX96(d,h,w+1),   bx01, u1);
            masked_b(pb, tg, IDX96(d+1,h,w),   bx10, u2);
            masked_b(pb, tg, IDX96(d+1,h,w+1), bx11, u3);
            float bz00 = bzp[IDX96(d,h,w)],   bz01 = bzp[IDX96(d,h,w+1)];
            float bz10 = bzp[IDX96(d+1,h,w)], bz11 = bzp[IDX96(d+1,h,w+1)];
            float jy = 0.5f*((bx00 - bx01) + (bx10 - bx11))
                     - 0.5f*((bz00 - bz10) + (bz01 - bz11));
            g_jy[(d*96 + h)*95 + w] = jy;
            emit_q(1, d*96 + h, w, 95, jy);
        }
        if (d < 95 && h < 95) {    // jz: (95,95,96)
            float bx00, by00, bx01, by01, bx10, by10, bx11, by11;
            masked_b(pb, tg, IDX96(d,h,w),     bx00, by00);
            masked_b(pb, tg, IDX96(d,h+1,w),   bx01, by01);
            masked_b(pb, tg, IDX96(d+1,h,w),   bx10, by10);
            masked_b(pb, tg, IDX96(d+1,h+1,w), bx11, by11);
            float jz = 0.5f*((by00 - by10) + (by01 - by11))
                     - 0.5f*((bx00 - bx01) + (bx10 - bx11));
            g_jz[(d*95 + h)*96 + w] = jz;
            emit_q(2, d*95 + h, w, 96, jz);
        }
    }
}

// ---------------- packed compare-exchange: alu (HMNMX2) and fma-pipe emu ----------------
template<bool ASC>
__device__ __forceinline__ void ce2s(__half2& a, __half2& b) {
    __half2 mn = __hmin2(a, b);
    __half2 mx = __hmax2(a, b);
    if (ASC) { a = mn; b = mx; } else { a = mx; b = mn; }
}

// fma-pipe comparator: mn = (a+b)/2 - |a-b|/2, mx = (a+b)/2 + |a-b|/2.
// <=1.5 fp16 ulp; NEVER sees +inf (pads excluded by the prune invariant).
template<bool ASC>
__device__ __forceinline__ void ce2e(__half2& a, __half2& b) {
    const __half2 H05 = __floats2half2_rn(0.5f, 0.5f);
    const __half2 M05 = __floats2half2_rn(-0.5f, -0.5f);
    __half2 s2 = __hmul2(__hadd2(a, b), H05);
    __half2 ad = __habs2(__hsub2(a, b));
    __half2 mn = __hfma2(ad, M05, s2);
    __half2 mx = __hfma2(ad, H05, s2);
    if (ASC) { a = mn; b = mx; } else { a = mx; b = mn; }
}

// 25% of comparators ((lo&3)==0: the measured optimum — r10/r15 best at 396us;
// r12 (2/7, %7) and r16 (37.5%, &7) both regressed: latency-bound, not
// pipe-balance-bound) go to the fma pipe.
template<bool ASC>
__device__ __forceinline__ void ce2sel(__half2& a, __half2& b, int lowire) {
    if ((lowire & 3) == 0) ce2e<ASC>(a, b);
    else                   ce2s<ASC>(a, b);
}

// Batcher OEM, template-constant indices only (register-resident).
// Pad prune: wires >= 125 hold +inf pads that never move under ascending
// comparators; any comparator whose HIGH wire is >= 125 is an exact no-op.
template<int LO, int N, int R, bool ASC>
__device__ __forceinline__ void oem_merge(__half2* v) {
    constexpr int M = 2 * R;
    if constexpr (M < N) {
        oem_merge<LO,     N, M, ASC>(v);
        oem_merge<LO + R, N, M, ASC>(v);
        #pragma unroll
        for (int i = LO + R; i + R < LO + N; i += M)
            if (i + R < 125) ce2sel<ASC>(v[i], v[i + R], i);
    } else {
        if constexpr (LO + R < 125) ce2sel<ASC>(v[LO], v[LO + R], LO);
    }
}

template<int LO, int N, bool ASC>
__device__ __forceinline__ void oem_sort(__half2* v) {
    if constexpr (N > 1) {
        oem_sort<LO,       N/2, ASC>(v);
        oem_sort<LO + N/2, N/2, ASC>(v);
        oem_merge<LO, N, 1, ASC>(v);
    }
}

// ---------------- fused median kernel (r10/r15 configuration, best measured) ----------------
__device__ __forceinline__ const float* med_src(const float* pb, int sel) {
    switch (sel) {
        case 0: return g_jx;
        case 1: return g_jy;
        case 2: return g_jz;
        case 3: return g_bxm;
        case 4: return g_bym;
        case 5: return pb;            // bx_p
        default: return pb + NVOX;    // by_p
    }
}

__global__ __launch_bounds__(128)
void median_all_kernel(const float* __restrict__ pb) {
    int b = blockIdx.x;
    int sel, base;
    if      (b < PB0)                       { sel = 0; base = b; }
    else if (b < PB0+PB1)                   { sel = 1; base = b - PB0; }
    else if (b < PB0+PB1+PB2)               { sel = 2; base = b - (PB0+PB1); }
    else if (b < PB0+PB1+PB2+1*PBB)         { sel = 3; base = b - (PB0+PB1+PB2); }
    else if (b < PB0+PB1+PB2+2*PBB)         { sel = 4; base = b - (PB0+PB1+PB2+1*PBB); }
    else if (b < PB0+PB1+PB2+3*PBB)         { sel = 5; base = b - (PB0+PB1+PB2+2*PBB); }
    else                                    { sel = 6; base = b - (PB0+PB1+PB2+3*PBB); }

    int D, H, W;
    if      (sel == 0) { D = 96; H = 95; W = 95; }
    else if (sel == 1) { D = 95; H = 96; W = 95; }
    else if (sel == 2) { D = 95; H = 95; W = 96; }
    else               { D = 96; H = 96; W = 96; }

    const int PW = 48;
    int npairs = D * H * PW;

    int i = base * 128 + threadIdx.x;
    double local = 0.0;
    if (i < npairs) {
        int hp = H * PW;
        int d = i / hp;
        int r = i - d * hp;
        int h = r / PW;
        int t = r - h * PW;
        int w0 = 2 * t;
        bool have1 = (w0 + 1 < W);

        int rd[5], rh[5];
        #pragma unroll
        for (int o = 0; o < 5; o++) {
            int c;
            c = d + o - 2; rd[o] = (c < 0) ? -c : ((c >= D) ? 2*D - 2 - c : c);
            c = h + o - 2; rh[o] = (c < 0) ? -c : ((c >= H) ? 2*H - 2 - c : c);
        }

        // exact fp32 centers
        const float* __restrict__ src = med_src(pb, sel);
        const float* crow = src + (d*H + h) * W + w0;
        float c0f = __ldg(crow);
        float c1f = have1 ? __ldg(crow + 1) : 0.0f;

        // pre-paired fp16 window loads: Q[w0 + o], o = 0..4 per row
        const __half2* __restrict__ q = g_q[sel];
        __half2 v[128];
        int idx = 0;
        #pragma unroll
        for (int dd = 0; dd < 5; dd++) {
            #pragma unroll
            for (int hh = 0; hh < 5; hh++) {
                const __half2* qrow = q + (rd[dd]*H + rh[hh]) * QSTRIDE + w0;
                v[idx++] = qrow[0];
                v[idx++] = qrow[1];
                v[idx++] = qrow[2];
                v[idx++] = qrow[3];
                v[idx++] = qrow[4];
            }
        }
        const float FINF = __int_as_float(0x7f800000);
        __half2 INF2 = __floats2half2_rn(FINF, FINF);
        v[125] = INF2; v[126] = INF2; v[127] = INF2;

        // Batcher OEM, both ascending; pads pinned at v[125..127] (pruned).
        oem_sort<0,  64, true>(v);
        oem_sort<64, 64, true>(v);

        // rank-63 (1-based) of A = v[0..62] U B = v[64..124]:
        //   med = min( v[62], min over i=2..62 of max(v[i-1], v[126-i]) )
        __half2 m0 = __hmax2(v[1], v[124]);
        __half2 m1 = __hmax2(v[2], v[123]);
        __half2 m2 = __hmax2(v[3], v[122]);
        __half2 m3 = __hmax2(v[4], v[121]);
        #pragma unroll
        for (int t2 = 6; t2 <= 62; t2 += 4) {
            m0 = __hmin2(m0, __hmax2(v[t2-1], v[126-t2]));
            if (t2+1 <= 62) m1 = __hmin2(m1, __hmax2(v[t2],   v[125-t2]));
            if (t2+2 <= 62) m2 = __hmin2(m2, __hmax2(v[t2+1], v[124-t2]));
            if (t2+3 <= 62) m3 = __hmin2(m3, __hmax2(v[t2+2], v[123-t2]));
        }
        __half2 med2 = __hmin2(__hmin2(m0, m1),
                               __hmin2(m2, __hmin2(m3, v[62])));

        float med0 = __low2float(med2);
        float med1 = __high2float(med2);
        float d0 = med0 - c0f;
        local = (double)(d0 * d0);
        if (have1) {
            float d1 = med1 - c1f;
            local += (double)(d1 * d1);
        }
    }
    local = warp_red(local);
    if ((threadIdx.x & 31) == 0) atomicAdd(&g_acc[sel], local);
}

// ---------------- finalize (reads accumulators, then resets them; static
// zero-init makes the very first call correct) ----------------
__global__ void finalize_kernel(float* __restrict__ out, int out_size) {
    if (blockIdx.x != 0 || threadIdx.x != 0) return;
    double n95 = (double)NDIV;
    double mp = g_acc[7] / n95;
    double mt = g_acc[9] / n95;
    double o[6];
    o[0] = mp;
    o[1] = g_acc[8] / n95 - mp * mp;
    o[2] = mt;
    o[3] = g_acc[10] / n95 - mt * mt;
    o[4] = (g_acc[0] + g_acc[1] + g_acc[2]) / (double)NJ;
    o[5] = (g_acc[3] + g_acc[4] + g_acc[5] + g_acc[6]) / (double)NVOX;
    for (int k = 0; k < 6 && k < out_size; k++) out[k] = (float)o[k];
    #pragma unroll
    for (int k = 0; k < 12; k++) g_acc[k] = 0.0;
}

// ---------------- launch ----------------
extern "C" void kernel_launch(void* const* d_in, const int* in_sizes, int n_in,
                              void* d_out, int out_size) {
    const float* pb = (const float*)d_in[0];   // pred_b  (3,96^3)
    const float* pz = (const float*)d_in[1];   // pred_z  (96^3)
    const float* tg = (const float*)d_in[2];   // targets (3,96^3)
    float* out = (float*)d_out;

    prep_all_kernel<<<NBD + NBM + NBJ, 128>>>(pb, pz, tg);
    median_all_kernel<<<PB0 + PB1 + PB2 + 4*PBB, 128>>>(pb);
    finalize_kernel<<<1, 32>>>(out, out_size);
}